// round 12
// baseline (speedup 1.0000x reference)
#include <cuda_runtime.h>

// Fused 2-layer LSTM + dense. B=2048, T=128, D=H1=128, H2=64, OUT=64.
// grid=128 CTAs x 512 threads; one CTA per 16 batch rows.
// GATE-INTERLEAVED weights: WT[k][4j+g] -> each thread owns all 4 gates of
// one unit => LSTM cell update fully in registers (no gbuf, no elementwise
// phase, 2 barriers/step). h1/h2 ping-pong buffers make fused writes safe.

#define B_TOT 2048
#define T_LEN 128
#define D_IN  128
#define H1    128
#define H2    64
#define OUTD  64
#define NB    16
#define NTH   512
#define ST2   36     // dup'd activation row stride (floats): 32 data + 4 pad

typedef unsigned long long ull;

// k-major, gate-interleaved: WT[k][4*unit+gate]
__device__ float WT1I[128 * 512];
__device__ float WT1H[128 * 512];
__device__ float WT2I[128 * 256];
__device__ float WT2H[64 * 256];

__device__ __forceinline__ void fma2(ull &d, ull a, ull b) {
    asm("fma.rn.f32x2 %0, %1, %2, %0;" : "+l"(d) : "l"(a), "l"(b));
}
__device__ __forceinline__ ull pack2(float lo, float hi) {
    return (ull)__float_as_uint(lo) | ((ull)__float_as_uint(hi) << 32);
}
__device__ __forceinline__ float lo2(ull v) { return __uint_as_float((unsigned)v); }
__device__ __forceinline__ float hi2(ull v) { return __uint_as_float((unsigned)(v >> 32)); }

__device__ __forceinline__ float sigm(float v) {
    return __fdividef(1.0f, 1.0f + __expf(-v));
}
__device__ __forceinline__ float tanh_(float v) {
    return 2.0f * sigm(2.0f * v) - 1.0f;
}

// ---------------- weight transpose kernel (gate-interleave) ----------------
__global__ void transpose_kernel(const float* __restrict__ w_ih1,
                                 const float* __restrict__ w_hh1,
                                 const float* __restrict__ w_ih2,
                                 const float* __restrict__ w_hh2) {
    int idx = blockIdx.x * blockDim.x + threadIdx.x;
    if (idx < 65536) {                       // w_ih1: (512,128)
        int row = idx >> 7, k = idx & 127;
        int g = row >> 7, j = row & 127;
        WT1I[k * 512 + 4 * j + g] = w_ih1[idx];
    } else if (idx < 131072) {               // w_hh1: (512,128)
        int i = idx - 65536;
        int row = i >> 7, k = i & 127;
        int g = row >> 7, j = row & 127;
        WT1H[k * 512 + 4 * j + g] = w_hh1[i];
    } else if (idx < 163840) {               // w_ih2: (256,128)
        int i = idx - 131072;
        int row = i >> 7, k = i & 127;
        int g = row >> 6, j = row & 63;
        WT2I[k * 256 + 4 * j + g] = w_ih2[i];
    } else if (idx < 180224) {               // w_hh2: (256,64)
        int i = idx - 163840;
        int row = i >> 6, k = i & 63;
        int g = row >> 6, j = row & 63;
        WT2H[k * 256 + 4 * j + g] = w_hh2[i];
    }
}

// M1 k-row: 4 dup'd rows (2 LDS.128), w.x=(i,f), w.y=(g,o). 8 FFMA2.
__device__ __forceinline__ void mmrow1(ull (&aif)[4], ull (&ago)[4],
                                       ulonglong2 w, const float* __restrict__ xr) {
    ulonglong2 a = *(const ulonglong2*)(xr + 0);    // rows 0,1 (dup'd)
    ulonglong2 b = *(const ulonglong2*)(xr + 4);    // rows 2,3
    fma2(aif[0], a.x, w.x); fma2(ago[0], a.x, w.y);
    fma2(aif[1], a.y, w.x); fma2(ago[1], a.y, w.y);
    fma2(aif[2], b.x, w.x); fma2(ago[2], b.x, w.y);
    fma2(aif[3], b.y, w.x); fma2(ago[3], b.y, w.y);
}

// M2 k-row: 2 dup'd rows (1 LDS.128). 4 FFMA2.
__device__ __forceinline__ void mmrow2(ull (&bif)[2], ull (&bgo)[2],
                                       ulonglong2 w, const float* __restrict__ xr) {
    ulonglong2 a = *(const ulonglong2*)(xr);        // rows 0,1 (dup'd)
    fma2(bif[0], a.x, w.x); fma2(bgo[0], a.x, w.y);
    fma2(bif[1], a.y, w.x); fma2(bgo[1], a.y, w.y);
}

// Accumulate K k-rows, 8-deep double-buffered weight prefetch.
template<int WSTR, int K>
__device__ __forceinline__ void mmacc1(ull (&aif)[4], ull (&ago)[4],
                                       const ulonglong2* __restrict__ w,
                                       const float* __restrict__ xb) {
    ulonglong2 wb0[4], wb1[4];
#pragma unroll
    for (int u = 0; u < 4; u++) wb0[u] = w[u * WSTR];
#pragma unroll
    for (int u = 0; u < 4; u++) wb1[u] = w[(4 + u) * WSTR];
#pragma unroll 1
    for (int kb = 0; kb < K; kb += 8) {
#pragma unroll
        for (int u = 0; u < 4; u++) mmrow1(aif, ago, wb0[u], xb + (kb + u) * ST2);
        if (kb + 8 < K) {
#pragma unroll
            for (int u = 0; u < 4; u++) wb0[u] = w[(kb + 8 + u) * WSTR];
        }
#pragma unroll
        for (int u = 0; u < 4; u++) mmrow1(aif, ago, wb1[u], xb + (kb + 4 + u) * ST2);
        if (kb + 12 < K) {
#pragma unroll
            for (int u = 0; u < 4; u++) wb1[u] = w[(kb + 12 + u) * WSTR];
        }
    }
}

template<int WSTR, int K>
__device__ __forceinline__ void mmacc2(ull (&bif)[2], ull (&bgo)[2],
                                       const ulonglong2* __restrict__ w,
                                       const float* __restrict__ xb) {
    ulonglong2 wb0[4], wb1[4];
#pragma unroll
    for (int u = 0; u < 4; u++) wb0[u] = w[u * WSTR];
#pragma unroll
    for (int u = 0; u < 4; u++) wb1[u] = w[(4 + u) * WSTR];
#pragma unroll 1
    for (int kb = 0; kb < K; kb += 8) {
#pragma unroll
        for (int u = 0; u < 4; u++) mmrow2(bif, bgo, wb0[u], xb + (kb + u) * ST2);
        if (kb + 8 < K) {
#pragma unroll
            for (int u = 0; u < 4; u++) wb0[u] = w[(kb + 8 + u) * WSTR];
        }
#pragma unroll
        for (int u = 0; u < 4; u++) mmrow2(bif, bgo, wb1[u], xb + (kb + 4 + u) * ST2);
        if (kb + 12 < K) {
#pragma unroll
            for (int u = 0; u < 4; u++) wb1[u] = w[(kb + 12 + u) * WSTR];
        }
    }
}

// ---------------- main fused kernel ----------------
__global__ void __launch_bounds__(NTH, 1)
lstm_main(const float* __restrict__ x,
          const float* __restrict__ b_ih1, const float* __restrict__ b_hh1,
          const float* __restrict__ b_ih2, const float* __restrict__ b_hh2,
          const float* __restrict__ w_dense, const float* __restrict__ b_dense,
          float* __restrict__ out) {
    extern __shared__ float sm[];
    float* xbuf = sm;                     // [128][ST2] x_t duplicated
    float* h1a  = xbuf + 128 * ST2;       // [128][ST2] h1 ping
    float* h1b  = h1a  + 128 * ST2;       // [128][ST2] h1 pong
    float* h2a  = h1b  + 128 * ST2;       // [64][ST2]  h2 ping
    float* h2b  = h2a  + 64 * ST2;        // [64][ST2]  h2 pong

    const int t  = threadIdx.x;
    const int b0 = blockIdx.x * NB;

    for (int i = t; i < (128 + 256 + 128) * ST2; i += NTH) sm[i] = 0.0f;

    // ---- M1 role: unit j1 (8/warp), row-quarter rq1 (4 rows) ----
    const int j1  = t >> 2;               // 0..127
    const int rq1 = t & 3;                // rows 4*rq1..4*rq1+3
    const ull b1if = pack2(b_ih1[j1]       + b_hh1[j1],
                           b_ih1[128 + j1] + b_hh1[128 + j1]);
    const ull b1go = pack2(b_ih1[256 + j1] + b_hh1[256 + j1],
                           b_ih1[384 + j1] + b_hh1[384 + j1]);

    // ---- M2 role: unit j2 (4/warp), row-eighth rq2 (2 rows) ----
    const int j2  = t >> 3;               // 0..63
    const int rq2 = t & 7;                // rows 2*rq2..2*rq2+1
    const ull b2if = pack2(b_ih2[j2]       + b_hh2[j2],
                           b_ih2[64 + j2]  + b_hh2[64 + j2]);
    const ull b2go = pack2(b_ih2[128 + j2] + b_hh2[128 + j2],
                           b_ih2[192 + j2] + b_hh2[192 + j2]);

    float c1s[4], c2s[2];
#pragma unroll
    for (int i = 0; i < 4; i++) c1s[i] = 0.0f;
    c2s[0] = c2s[1] = 0.0f;

    const ulonglong2* wq1i = (const ulonglong2*)WT1I + j1;   // row stride 128 u2
    const ulonglong2* wq1h = (const ulonglong2*)WT1H + j1;
    const ulonglong2* wq2i = (const ulonglong2*)WT2I + j2;   // row stride 64 u2
    const ulonglong2* wq2h = (const ulonglong2*)WT2H + j2;   // row stride 64 u2

    const int xr_row = t >> 5;            // 0..15
    const int xr_d0  = (t & 31) * 4;      // 0..124

    float* h1r = h1a; float* h1w = h1b;
    float* h2r = h2a; float* h2w = h2b;

    __syncthreads();

#pragma unroll 1
    for (int step = 0; step < T_LEN; ++step) {
        // ---- stage x_t transposed + duplicated ----
        {
            const float* xr = x + ((b0 + xr_row) * T_LEN + step) * D_IN + xr_d0;
            float4 u = *(const float4*)xr;
            *(float2*)&xbuf[(xr_d0 + 0) * ST2 + 2 * xr_row] = make_float2(u.x, u.x);
            *(float2*)&xbuf[(xr_d0 + 1) * ST2 + 2 * xr_row] = make_float2(u.y, u.y);
            *(float2*)&xbuf[(xr_d0 + 2) * ST2 + 2 * xr_row] = make_float2(u.z, u.z);
            *(float2*)&xbuf[(xr_d0 + 3) * ST2 + 2 * xr_row] = make_float2(u.w, u.w);
        }
        __syncthreads();   // S1: xbuf ready; all prev-step M2 reads complete

        // ---- M1 + fused cell update: gates for unit j1, rows 4rq1.. ----
        {
            ull aif[4], ago[4];
#pragma unroll
            for (int r = 0; r < 4; r++) { aif[r] = b1if; ago[r] = b1go; }
            mmacc1<128, 128>(aif, ago, wq1i, xbuf + 8 * rq1);
            mmacc1<128, 128>(aif, ago, wq1h, h1r  + 8 * rq1);
#pragma unroll
            for (int r = 0; r < 4; r++) {
                float iv = sigm(lo2(aif[r]));
                float fv = sigm(hi2(aif[r]));
                float gv = tanh_(lo2(ago[r]));
                float ov = sigm(hi2(ago[r]));
                c1s[r] = fv * c1s[r] + iv * gv;
                float hv = ov * tanh_(c1s[r]);
                *(float2*)&h1w[j1 * ST2 + 2 * (4 * rq1 + r)] = make_float2(hv, hv);
            }
        }
        __syncthreads();   // S2: h1(step) complete; h1r/xbuf reads done

        // ---- M2 + fused cell update: gates for unit j2, rows 2rq2.. ----
        {
            ull bif[2], bgo[2];
            bif[0] = b2if; bif[1] = b2if;
            bgo[0] = b2go; bgo[1] = b2go;
            mmacc2<64, 128>(bif, bgo, wq2i, h1w + 4 * rq2);   // h1 of this step
            mmacc2<64, 64> (bif, bgo, wq2h, h2r + 4 * rq2);   // h2 of prev step
#pragma unroll
            for (int r = 0; r < 2; r++) {
                float iv = sigm(lo2(bif[r]));
                float fv = sigm(hi2(bif[r]));
                float gv = tanh_(lo2(bgo[r]));
                float ov = sigm(hi2(bgo[r]));
                c2s[r] = fv * c2s[r] + iv * gv;
                float hv = ov * tanh_(c2s[r]);
                *(float2*)&h2w[j2 * ST2 + 2 * (2 * rq2 + r)] = make_float2(hv, hv);
            }
        }
        // swap ping-pong (next S1 orders all cross-thread hazards)
        { float* tmp = h1r; h1r = h1w; h1w = tmp; }
        { float* tmp = h2r; h2r = h2w; h2w = tmp; }
    }

    __syncthreads();   // final h2 (in h2r after last swap) visible to all

    // ---- dense + relu on final h2 (duplicated rows: row r at offset 2r) ----
    {
        int o  = t & 63;
        int r0 = (t >> 6) * 2;           // 2 rows per thread
        float bd = b_dense[o];
        float a0 = bd, a1 = bd;
        const float* wd = w_dense + o * 64;
#pragma unroll 8
        for (int k = 0; k < 64; k++) {
            float wv = wd[k];
            const float* h = &h2r[k * ST2 + 2 * r0];
            a0 += wv * h[0];
            a1 += wv * h[2];
        }
        out[(b0 + r0 + 0) * OUTD + o] = fmaxf(a0, 0.0f);
        out[(b0 + r0 + 1) * OUTD + o] = fmaxf(a1, 0.0f);
    }
}

#define SMEM_BYTES ((128 + 256 + 128) * ST2 * 4)

extern "C" void kernel_launch(void* const* d_in, const int* in_sizes, int n_in,
                              void* d_out, int out_size) {
    const float* x       = (const float*)d_in[0];
    const float* w_ih1   = (const float*)d_in[1];
    const float* w_hh1   = (const float*)d_in[2];
    const float* b_ih1   = (const float*)d_in[3];
    const float* b_hh1   = (const float*)d_in[4];
    const float* w_ih2   = (const float*)d_in[5];
    const float* w_hh2   = (const float*)d_in[6];
    const float* b_ih2   = (const float*)d_in[7];
    const float* b_hh2   = (const float*)d_in[8];
    const float* w_dense = (const float*)d_in[9];
    const float* b_dense = (const float*)d_in[10];
    float* out = (float*)d_out;

    static int attr_set = 0;
    if (!attr_set) {
        cudaFuncSetAttribute(lstm_main, cudaFuncAttributeMaxDynamicSharedMemorySize, SMEM_BYTES);
        attr_set = 1;
    }

    transpose_kernel<<<704, 256>>>(w_ih1, w_hh1, w_ih2, w_hh2);
    lstm_main<<<B_TOT / NB, NTH, SMEM_BYTES>>>(x, b_ih1, b_hh1, b_ih2, b_hh2,
                                               w_dense, b_dense, out);
}

// round 14
// speedup vs baseline: 1.5119x; 1.5119x over previous
#include <cuda_runtime.h>

// Fused 2-layer LSTM + dense. B=2048, T=128, D=H1=128, H2=64, OUT=64.
// grid=256 CTAs x 256 threads, NB=8 rows per CTA => 2 resident CTAs/SM.
// The two CTAs' barrier phases interleave, hiding prefetch/LDS latency that
// bounded the single-CTA version. Per-SM fma work, LDS wf and weight L2
// traffic are identical to the best previous kernel (R8 structure).
// L1: colchunk(128) x khalf(2) tiles; L2: colchunk(64) x kquarter(4).

#define B_TOT 2048
#define T_LEN 128
#define D_IN  128
#define H1    128
#define H2    64
#define OUTD  64
#define NB    8
#define NTH   256
#define ST2   20     // dup'd activation row stride (floats): 16 data + 4 pad
#define GROW  1040   // gbuf row stride (floats): 1024 cols + 16 pad

typedef unsigned long long ull;

// k-major transposed weights: WT[k][g] = W[g][k]
__device__ float WT1I[128 * 512];
__device__ float WT1H[128 * 512];
__device__ float WT2I[128 * 256];
__device__ float WT2H[64 * 256];

__device__ __forceinline__ void fma2(ull &d, ull a, ull b) {
    asm("fma.rn.f32x2 %0, %1, %2, %0;" : "+l"(d) : "l"(a), "l"(b));
}
__device__ __forceinline__ ull pack2(float lo, float hi) {
    return (ull)__float_as_uint(lo) | ((ull)__float_as_uint(hi) << 32);
}
__device__ __forceinline__ float lo2(ull v) { return __uint_as_float((unsigned)v); }
__device__ __forceinline__ float hi2(ull v) { return __uint_as_float((unsigned)(v >> 32)); }

__device__ __forceinline__ float sigm(float v) {
    return __fdividef(1.0f, 1.0f + __expf(-v));
}
__device__ __forceinline__ float tanh_(float v) {
    return 2.0f * sigm(2.0f * v) - 1.0f;
}

// ---------------- weight transpose kernel ----------------
__global__ void transpose_kernel(const float* __restrict__ w_ih1,
                                 const float* __restrict__ w_hh1,
                                 const float* __restrict__ w_ih2,
                                 const float* __restrict__ w_hh2) {
    int idx = blockIdx.x * blockDim.x + threadIdx.x;
    if (idx < 65536) {                       // w_ih1: (512,128)
        int g = idx >> 7, k = idx & 127;
        WT1I[k * 512 + g] = w_ih1[idx];
    } else if (idx < 131072) {               // w_hh1: (512,128)
        int i = idx - 65536; int g = i >> 7, k = i & 127;
        WT1H[k * 512 + g] = w_hh1[i];
    } else if (idx < 163840) {               // w_ih2: (256,128)
        int i = idx - 131072; int g = i >> 7, k = i & 127;
        WT2I[k * 256 + g] = w_ih2[i];
    } else if (idx < 180224) {               // w_hh2: (256,64)
        int i = idx - 163840; int g = i >> 6, k = i & 63;
        WT2H[k * 256 + g] = w_hh2[i];
    }
}

// One k-row: 8 dup'd rows (4 LDS.128), 2 weight pairs. 16 FFMA2.
__device__ __forceinline__ void mmrow2(ull (&a0)[8], ull (&a1)[8],
                                       ulonglong2 w, const float* __restrict__ xr) {
    ulonglong2 a = *(const ulonglong2*)(xr + 0);    // rows 0,1 (dup'd)
    ulonglong2 b = *(const ulonglong2*)(xr + 4);    // rows 2,3
    ulonglong2 c = *(const ulonglong2*)(xr + 8);    // rows 4,5
    ulonglong2 d = *(const ulonglong2*)(xr + 12);   // rows 6,7
    fma2(a0[0], a.x, w.x); fma2(a1[0], a.x, w.y);
    fma2(a0[1], a.y, w.x); fma2(a1[1], a.y, w.y);
    fma2(a0[2], b.x, w.x); fma2(a1[2], b.x, w.y);
    fma2(a0[3], b.y, w.x); fma2(a1[3], b.y, w.y);
    fma2(a0[4], c.x, w.x); fma2(a1[4], c.x, w.y);
    fma2(a0[5], c.y, w.x); fma2(a1[5], c.y, w.y);
    fma2(a0[6], d.x, w.x); fma2(a1[6], d.x, w.y);
    fma2(a0[7], d.y, w.x); fma2(a1[7], d.y, w.y);
}

// Accumulate K k-rows starting at k0. WSTR = ulonglong2 per weight row.
// wq pre-offset by the thread's 16B column chunk.
template<int WSTR, int K>
__device__ __forceinline__ void mmacc(ull (&a0)[8], ull (&a1)[8],
                                      const ulonglong2* __restrict__ wq,
                                      const float* __restrict__ xb, int k0) {
    const ulonglong2* w = wq + k0 * WSTR;
    const float* xbase = xb + k0 * ST2;
    ulonglong2 wb0[4], wb1[4];
#pragma unroll
    for (int u = 0; u < 4; u++) wb0[u] = w[u * WSTR];
#pragma unroll
    for (int u = 0; u < 4; u++) wb1[u] = w[(4 + u) * WSTR];
#pragma unroll 1
    for (int kb = 0; kb < K; kb += 8) {
#pragma unroll
        for (int u = 0; u < 4; u++) mmrow2(a0, a1, wb0[u], xbase + (kb + u) * ST2);
        if (kb + 8 < K) {
#pragma unroll
            for (int u = 0; u < 4; u++) wb0[u] = w[(kb + 8 + u) * WSTR];
        }
#pragma unroll
        for (int u = 0; u < 4; u++) mmrow2(a0, a1, wb1[u], xbase + (kb + 4 + u) * ST2);
        if (kb + 12 < K) {
#pragma unroll
            for (int u = 0; u < 4; u++) wb1[u] = w[(kb + 12 + u) * WSTR];
        }
    }
}

// stage: 8 rows x 4 cols into row-major gbuf; lane-consecutive float4 stores.
__device__ __forceinline__ void stage8(float* gc, ull (&a0)[8], ull (&a1)[8]) {
#pragma unroll
    for (int r = 0; r < 8; r++)
        *(float4*)(gc + r * GROW) = make_float4(lo2(a0[r]), hi2(a0[r]),
                                                lo2(a1[r]), hi2(a1[r]));
}

// ---------------- main fused kernel ----------------
__global__ void __launch_bounds__(NTH, 2)
lstm_main(const float* __restrict__ x,
          const float* __restrict__ b_ih1, const float* __restrict__ b_hh1,
          const float* __restrict__ b_ih2, const float* __restrict__ b_hh2,
          const float* __restrict__ w_dense, const float* __restrict__ b_dense,
          float* __restrict__ out) {
    extern __shared__ float sm[];
    float* xbuf  = sm;                    // [128][ST2] x_t  duplicated
    float* h1buf = xbuf  + 128 * ST2;     // [128][ST2] h1   duplicated
    float* h2buf = h1buf + 128 * ST2;     // [64][ST2]  h2   duplicated
    float* gbuf  = h2buf + 64 * ST2;      // [8][GROW]  gate staging, row-major

    const int t  = threadIdx.x;
    const int b0 = blockIdx.x * NB;

    for (int i = t; i < (128 + 128 + 64) * ST2 + 8 * GROW; i += NTH) sm[i] = 0.0f;

    // ---- layer1 matmul role: cols 4q1..4q1+3 (all 8 rows), k-half kh1 ----
    const int q1  = t & 127;
    const int kh1 = t >> 7;               // 0/1
    ull b1a = 0, b1b = 0;
    if (kh1 == 0) {
        b1a = pack2(b_ih1[4 * q1]     + b_hh1[4 * q1],
                    b_ih1[4 * q1 + 1] + b_hh1[4 * q1 + 1]);
        b1b = pack2(b_ih1[4 * q1 + 2] + b_hh1[4 * q1 + 2],
                    b_ih1[4 * q1 + 3] + b_hh1[4 * q1 + 3]);
    }

    // ---- layer2 matmul role: cols 4q2..4q2+3 (all 8 rows), k-quarter kq ----
    const int q2  = t & 63;
    const int kq  = t >> 6;               // 0..3
    ull b2a = 0, b2b = 0;
    if (kq == 0) {
        b2a = pack2(b_ih2[4 * q2]     + b_hh2[4 * q2],
                    b_ih2[4 * q2 + 1] + b_hh2[4 * q2 + 1]);
        b2b = pack2(b_ih2[4 * q2 + 2] + b_hh2[4 * q2 + 2],
                    b_ih2[4 * q2 + 3] + b_hh2[4 * q2 + 3]);
    }

    // elementwise roles
    const int j1  = t & 127;              // layer1 unit
    const int r0h = (t >> 7) * 4;         // 4 rows (2 groups x 4 = 8)
    const int j2  = t & 63;               // layer2 unit
    const int r0q = (t >> 6) * 2;         // 2 rows (4 groups x 2 = 8)

    float c1s[4], c2s[2];
#pragma unroll
    for (int i = 0; i < 4; i++) c1s[i] = 0.0f;
    c2s[0] = c2s[1] = 0.0f;

    const ulonglong2* wq1i = (const ulonglong2*)WT1I + q1;   // row stride 128 u2
    const ulonglong2* wq1h = (const ulonglong2*)WT1H + q1;
    const ulonglong2* wq2i = (const ulonglong2*)WT2I + q2;   // row stride 64 u2
    const ulonglong2* wq2h = (const ulonglong2*)WT2H + q2;

    const int xr_row = t >> 5;            // 0..7
    const int xr_d0  = (t & 31) * 4;      // 0..124

    __syncthreads();

#pragma unroll 1
    for (int step = 0; step < T_LEN; ++step) {
        // ---- stage x_t transposed + duplicated into xbuf[d][2r],[2r+1] ----
        {
            const float* xr = x + ((b0 + xr_row) * T_LEN + step) * D_IN + xr_d0;
            float4 u = *(const float4*)xr;
            *(float2*)&xbuf[(xr_d0 + 0) * ST2 + 2 * xr_row] = make_float2(u.x, u.x);
            *(float2*)&xbuf[(xr_d0 + 1) * ST2 + 2 * xr_row] = make_float2(u.y, u.y);
            *(float2*)&xbuf[(xr_d0 + 2) * ST2 + 2 * xr_row] = make_float2(u.z, u.z);
            *(float2*)&xbuf[(xr_d0 + 3) * ST2 + 2 * xr_row] = make_float2(u.w, u.w);
        }
        __syncthreads();   // S1: xbuf ready; prev-step gbuf/h2buf reads complete

        // ---- layer1 gates (k-half): bias + x·Wih1^T + h1·Whh1^T ----
        {
            ull a0[8], a1[8];
#pragma unroll
            for (int r = 0; r < 8; r++) { a0[r] = b1a; a1[r] = b1b; }
            mmacc<128, 64>(a0, a1, wq1i, xbuf,  kh1 * 64);
            mmacc<128, 64>(a0, a1, wq1h, h1buf, kh1 * 64);
            stage8(gbuf + kh1 * 512 + 4 * q1, a0, a1);
        }
        __syncthreads();   // S2: gbuf(L1) complete; xbuf/h1buf reads done

        // ---- layer1 elementwise: unit j1, rows r0h..r0h+3 (sum 2 partials) ----
        {
#pragma unroll
            for (int r = 0; r < 4; r++) {
                int row = r0h + r;
                const float* gr = gbuf + row * GROW;
                float gi = gr[j1]       + gr[512 + j1];
                float gf = gr[128 + j1] + gr[640 + j1];
                float gg = gr[256 + j1] + gr[768 + j1];
                float go = gr[384 + j1] + gr[896 + j1];
                float iv = sigm(gi);
                float fv = sigm(gf);
                float gv = tanh_(gg);
                float ov = sigm(go);
                c1s[r] = fv * c1s[r] + iv * gv;
                float hv = ov * tanh_(c1s[r]);
                *(float2*)&h1buf[j1 * ST2 + 2 * row] = make_float2(hv, hv);
            }
        }
        __syncthreads();   // S3: h1buf ready; gbuf(L1) reads done

        // ---- layer2 gates (k-quarter) ----
        {
            ull a0[8], a1[8];
#pragma unroll
            for (int r = 0; r < 8; r++) { a0[r] = b2a; a1[r] = b2b; }
            mmacc<64, 32>(a0, a1, wq2i, h1buf, kq * 32);
            mmacc<64, 16>(a0, a1, wq2h, h2buf, kq * 16);
            stage8(gbuf + kq * 256 + 4 * q2, a0, a1);
        }
        __syncthreads();   // S4: gbuf(L2) complete; h1buf/h2buf reads done

        // ---- layer2 elementwise: unit j2, rows r0q..r0q+1 (sum 4 partials) ----
        {
#pragma unroll
            for (int r = 0; r < 2; r++) {
                int row = r0q + r;
                const float* gr = gbuf + row * GROW;
                float gi = gr[j2]       + gr[256 + j2] + gr[512 + j2] + gr[768 + j2];
                float gf = gr[64 + j2]  + gr[320 + j2] + gr[576 + j2] + gr[832 + j2];
                float gg = gr[128 + j2] + gr[384 + j2] + gr[640 + j2] + gr[896 + j2];
                float go = gr[192 + j2] + gr[448 + j2] + gr[704 + j2] + gr[960 + j2];
                float iv = sigm(gi);
                float fv = sigm(gf);
                float gv = tanh_(gg);
                float ov = sigm(go);
                c2s[r] = fv * c2s[r] + iv * gv;
                float hv = ov * tanh_(c2s[r]);
                *(float2*)&h2buf[j2 * ST2 + 2 * row] = make_float2(hv, hv);
            }
        }
        // no barrier: next-step S1 orders gbuf/h2buf reads vs subsequent writes
    }

    __syncthreads();   // h2buf final values visible to all threads

    // ---- dense + relu on final h2 (duplicated rows: row r at offset 2r) ----
    {
        int o  = t & 63;
        int r0 = (t >> 6) * 2;           // 2 rows per thread
        float bd = b_dense[o];
        float a0 = bd, a1 = bd;
        const float* wd = w_dense + o * 64;
#pragma unroll 8
        for (int k = 0; k < 64; k++) {
            float wv = wd[k];
            const float* h = &h2buf[k * ST2 + 2 * r0];
            a0 += wv * h[0];
            a1 += wv * h[2];
        }
        out[(b0 + r0 + 0) * OUTD + o] = fmaxf(a0, 0.0f);
        out[(b0 + r0 + 1) * OUTD + o] = fmaxf(a1, 0.0f);
    }
}

#define SMEM_BYTES (((128 + 128 + 64) * ST2 + 8 * GROW) * 4)

extern "C" void kernel_launch(void* const* d_in, const int* in_sizes, int n_in,
                              void* d_out, int out_size) {
    const float* x       = (const float*)d_in[0];
    const float* w_ih1   = (const float*)d_in[1];
    const float* w_hh1   = (const float*)d_in[2];
    const float* b_ih1   = (const float*)d_in[3];
    const float* b_hh1   = (const float*)d_in[4];
    const float* w_ih2   = (const float*)d_in[5];
    const float* w_hh2   = (const float*)d_in[6];
    const float* b_ih2   = (const float*)d_in[7];
    const float* b_hh2   = (const float*)d_in[8];
    const float* w_dense = (const float*)d_in[9];
    const float* b_dense = (const float*)d_in[10];
    float* out = (float*)d_out;

    static int attr_set = 0;
    if (!attr_set) {
        cudaFuncSetAttribute(lstm_main, cudaFuncAttributeMaxDynamicSharedMemorySize, SMEM_BYTES);
        attr_set = 1;
    }

    transpose_kernel<<<704, 256>>>(w_ih1, w_hh1, w_ih2, w_hh2);
    lstm_main<<<B_TOT / NB, NTH, SMEM_BYTES>>>(x, b_ih1, b_hh1, b_ih2, b_hh2,
                                               w_dense, b_dense, out);
}

// round 15
// speedup vs baseline: 1.7807x; 1.1778x over previous
#include <cuda_runtime.h>

// Fused 2-layer LSTM + dense. B=2048, T=128, D=H1=128, H2=64, OUT=64.
// grid=128 x 512 threads; one CTA per 16 batch rows.
// Layer 2 runs ONE TIMESTEP BEHIND layer 1, so all matmul work (gates1(s) and
// gates2(s-1)) forms a single homogeneous phase with every input available:
//   MM(s): gates1(s) + gates2(s-1)      (reads abuf = [x(s), h1(s-1), h2(s-2)])
//   E(s):  cell1(s) + cell2(s-1) + stage x(s+1)   (writes abuf, reads gbuf)
// => 2 barriers/step, uniform 2816 FFMA2 per thread per step.
// Weights are concatenated k-major (WCAT1=[Wih1;Whh1], WCAT2=[Wih2;Whh2]) so
// each thread is one contiguous k-segment; activations concatenated likewise.

#define B_TOT 2048
#define T_LEN 128
#define D_IN  128
#define H1    128
#define H2    64
#define OUTD  64
#define NB    16
#define NTH   512
#define ST2   36     // dup'd activation row stride (floats): 32 data + 4 pad
#define AROWS 320    // abuf rows: x(128) + h1(128) + h2(64)
#define GROW  2080   // gbuf row stride: L1 2x520 + L2 4x260
#define GL2   1040   // L2 section base within a gbuf row

typedef unsigned long long ull;

// concatenated k-major weights: WCAT1[k][g] (256x512), WCAT2[k][g] (192x256)
__device__ float WCAT1[256 * 512];
__device__ float WCAT2[192 * 256];

__device__ __forceinline__ void fma2(ull &d, ull a, ull b) {
    asm("fma.rn.f32x2 %0, %1, %2, %0;" : "+l"(d) : "l"(a), "l"(b));
}
__device__ __forceinline__ ull pack2(float lo, float hi) {
    return (ull)__float_as_uint(lo) | ((ull)__float_as_uint(hi) << 32);
}
__device__ __forceinline__ float lo2(ull v) { return __uint_as_float((unsigned)v); }
__device__ __forceinline__ float hi2(ull v) { return __uint_as_float((unsigned)(v >> 32)); }

__device__ __forceinline__ float sigm(float v) {
    return __fdividef(1.0f, 1.0f + __expf(-v));
}
__device__ __forceinline__ float tanh_(float v) {
    return 2.0f * sigm(2.0f * v) - 1.0f;
}

// ---------------- weight transpose kernel ----------------
__global__ void transpose_kernel(const float* __restrict__ w_ih1,
                                 const float* __restrict__ w_hh1,
                                 const float* __restrict__ w_ih2,
                                 const float* __restrict__ w_hh2) {
    int idx = blockIdx.x * blockDim.x + threadIdx.x;
    if (idx < 65536) {                       // w_ih1 (512,128) -> WCAT1 rows 0-127
        int g = idx >> 7, k = idx & 127;
        WCAT1[k * 512 + g] = w_ih1[idx];
    } else if (idx < 131072) {               // w_hh1 (512,128) -> WCAT1 rows 128-255
        int i = idx - 65536; int g = i >> 7, k = i & 127;
        WCAT1[(128 + k) * 512 + g] = w_hh1[i];
    } else if (idx < 163840) {               // w_ih2 (256,128) -> WCAT2 rows 0-127
        int i = idx - 131072; int g = i >> 7, k = i & 127;
        WCAT2[k * 256 + g] = w_ih2[i];
    } else if (idx < 180224) {               // w_hh2 (256,64) -> WCAT2 rows 128-191
        int i = idx - 163840; int g = i >> 6, k = i & 63;
        WCAT2[(128 + k) * 256 + g] = w_hh2[i];
    }
}

// One k-row: 8 dup'd rows (4 broadcast LDS.128), 2 weight col-pairs. 16 FFMA2.
__device__ __forceinline__ void mmrow2(ull (&a0)[8], ull (&a1)[8],
                                       ulonglong2 w, const float* __restrict__ xr) {
    ulonglong2 a = *(const ulonglong2*)(xr + 0);
    ulonglong2 b = *(const ulonglong2*)(xr + 4);
    ulonglong2 c = *(const ulonglong2*)(xr + 8);
    ulonglong2 d = *(const ulonglong2*)(xr + 12);
    fma2(a0[0], a.x, w.x); fma2(a1[0], a.x, w.y);
    fma2(a0[1], a.y, w.x); fma2(a1[1], a.y, w.y);
    fma2(a0[2], b.x, w.x); fma2(a1[2], b.x, w.y);
    fma2(a0[3], b.y, w.x); fma2(a1[3], b.y, w.y);
    fma2(a0[4], c.x, w.x); fma2(a1[4], c.x, w.y);
    fma2(a0[5], c.y, w.x); fma2(a1[5], c.y, w.y);
    fma2(a0[6], d.x, w.x); fma2(a1[6], d.x, w.y);
    fma2(a0[7], d.y, w.x); fma2(a1[7], d.y, w.y);
}

// Accumulate K k-rows; w/xb fully pre-offset. WSTR = ulonglong2 per weight row.
template<int WSTR, int K>
__device__ __forceinline__ void mmacc(ull (&a0)[8], ull (&a1)[8],
                                      const ulonglong2* __restrict__ w,
                                      const float* __restrict__ xb) {
    ulonglong2 wb0[4], wb1[4];
#pragma unroll
    for (int u = 0; u < 4; u++) wb0[u] = w[u * WSTR];
#pragma unroll
    for (int u = 0; u < 4; u++) wb1[u] = w[(4 + u) * WSTR];
#pragma unroll 1
    for (int kb = 0; kb < K; kb += 8) {
#pragma unroll
        for (int u = 0; u < 4; u++) mmrow2(a0, a1, wb0[u], xb + (kb + u) * ST2);
        if (kb + 8 < K) {
#pragma unroll
            for (int u = 0; u < 4; u++) wb0[u] = w[(kb + 8 + u) * WSTR];
        }
#pragma unroll
        for (int u = 0; u < 4; u++) mmrow2(a0, a1, wb1[u], xb + (kb + 4 + u) * ST2);
        if (kb + 12 < K) {
#pragma unroll
            for (int u = 0; u < 4; u++) wb1[u] = w[(kb + 12 + u) * WSTR];
        }
    }
}

// stage 8 rows x 4 cols; lanes (consecutive q) give conflict-free STS.128.
__device__ __forceinline__ void stage8(float* gc, ull (&a0)[8], ull (&a1)[8]) {
#pragma unroll
    for (int r = 0; r < 8; r++)
        *(float4*)(gc + r * GROW) = make_float4(lo2(a0[r]), hi2(a0[r]),
                                                lo2(a1[r]), hi2(a1[r]));
}

// ---------------- main fused kernel ----------------
__global__ void __launch_bounds__(NTH, 1)
lstm_main(const float* __restrict__ x,
          const float* __restrict__ b_ih1, const float* __restrict__ b_hh1,
          const float* __restrict__ b_ih2, const float* __restrict__ b_hh2,
          const float* __restrict__ w_dense, const float* __restrict__ b_dense,
          float* __restrict__ out) {
    extern __shared__ float sm[];
    float* abuf = sm;                     // [320][ST2]: x | h1 | h2, dup'd
    float* gbuf = abuf + AROWS * ST2;     // [16][GROW] gate partial staging

    const int t  = threadIdx.x;
    const int b0 = blockIdx.x * NB;

    for (int i = t; i < AROWS * ST2 + 16 * GROW; i += NTH) sm[i] = 0.0f;

    // ---- MM-L1 role: t = kh1(1b) | rh1(1b) | q1(7b)  (q in low bits => broadcast LDS)
    const int q1  = t & 127;
    const int rh1 = (t >> 7) & 1;
    const int kh1 = (t >> 8) & 1;
    ull b1a = 0, b1b = 0;
    if (kh1 == 0) {
        b1a = pack2(b_ih1[4 * q1]     + b_hh1[4 * q1],
                    b_ih1[4 * q1 + 1] + b_hh1[4 * q1 + 1]);
        b1b = pack2(b_ih1[4 * q1 + 2] + b_hh1[4 * q1 + 2],
                    b_ih1[4 * q1 + 3] + b_hh1[4 * q1 + 3]);
    }

    // ---- MM-L2 role: t = kq2(2b) | rh2(1b) | q2(6b)
    const int q2  = t & 63;
    const int rh2 = (t >> 6) & 1;
    const int kq2 = t >> 7;               // 0..3
    ull b2a = 0, b2b = 0;
    if (kq2 == 0) {
        b2a = pack2(b_ih2[4 * q2]     + b_hh2[4 * q2],
                    b_ih2[4 * q2 + 1] + b_hh2[4 * q2 + 1]);
        b2b = pack2(b_ih2[4 * q2 + 2] + b_hh2[4 * q2 + 2],
                    b_ih2[4 * q2 + 3] + b_hh2[4 * q2 + 3]);
    }

    // ---- E roles
    const int j1  = t & 127;              // L1 unit, rows r0h..r0h+3
    const int r0h = (t >> 7) * 4;
    const int j2  = t & 63;               // L2 unit, rows r0q..r0q+1
    const int r0q = (t >> 6) * 2;

    float c1s[4], c2s[2];
#pragma unroll
    for (int i = 0; i < 4; i++) c1s[i] = 0.0f;
    c2s[0] = c2s[1] = 0.0f;

    // fully pre-offset matmul operands
    const ulonglong2* wL1 = (const ulonglong2*)WCAT1 + kh1 * 128 * 128 + q1;
    const float*      aL1 = abuf + (kh1 * 128) * ST2 + 16 * rh1;
    const ulonglong2* wL2 = (const ulonglong2*)WCAT2 + (kq2 * 48) * 64 + q2;
    const float*      aL2 = abuf + (128 + kq2 * 48) * ST2 + 16 * rh2;
    float* gL1 = gbuf + (rh1 * 8) * GROW + kh1 * 520 + 4 * q1;
    float* gL2 = gbuf + (rh2 * 8) * GROW + GL2 + kq2 * 260 + 4 * q2;

    // x staging role
    const int xr_row = t >> 5;            // 0..15
    const int xr_d0  = (t & 31) * 4;      // 0..124

    // prologue: stage x(0)
    {
        const float* xr = x + ((b0 + xr_row) * T_LEN + 0) * D_IN + xr_d0;
        float4 u = *(const float4*)xr;
        *(float2*)&abuf[(xr_d0 + 0) * ST2 + 2 * xr_row] = make_float2(u.x, u.x);
        *(float2*)&abuf[(xr_d0 + 1) * ST2 + 2 * xr_row] = make_float2(u.y, u.y);
        *(float2*)&abuf[(xr_d0 + 2) * ST2 + 2 * xr_row] = make_float2(u.z, u.z);
        *(float2*)&abuf[(xr_d0 + 3) * ST2 + 2 * xr_row] = make_float2(u.w, u.w);
    }
    __syncthreads();

#pragma unroll 1
    for (int s = 0; s <= T_LEN; ++s) {
        // prefetch x(s+1) into regs (consumed in E); hidden under MM
        float4 xreg;
        if (s < T_LEN - 1) {
            const float* xr = x + ((b0 + xr_row) * T_LEN + (s + 1)) * D_IN + xr_d0;
            xreg = *(const float4*)xr;
        }

        // ---- MM phase: gates1(s) and gates2(s-1) ----
        if (s < T_LEN) {
            ull a0[8], a1[8];
#pragma unroll
            for (int r = 0; r < 8; r++) { a0[r] = b1a; a1[r] = b1b; }
            mmacc<128, 128>(a0, a1, wL1, aL1);
            stage8(gL1, a0, a1);
        }
        if (s >= 1) {
            ull a0[8], a1[8];
#pragma unroll
            for (int r = 0; r < 8; r++) { a0[r] = b2a; a1[r] = b2b; }
            mmacc<64, 48>(a0, a1, wL2, aL2);
            stage8(gL2, a0, a1);
        }
        __syncthreads();   // gbuf complete; abuf reads done

        // ---- E phase: cell1(s), cell2(s-1), stage x(s+1) ----
        if (s < T_LEN) {
#pragma unroll
            for (int r = 0; r < 4; r++) {
                int row = r0h + r;
                const float* gr = gbuf + row * GROW;
                float gi = gr[j1]       + gr[520 + j1];
                float gf = gr[128 + j1] + gr[648 + j1];
                float gg = gr[256 + j1] + gr[776 + j1];
                float go = gr[384 + j1] + gr[904 + j1];
                float iv = sigm(gi);
                float fv = sigm(gf);
                float gv = tanh_(gg);
                float ov = sigm(go);
                c1s[r] = fv * c1s[r] + iv * gv;
                float hv = ov * tanh_(c1s[r]);
                *(float2*)&abuf[(128 + j1) * ST2 + 2 * row] = make_float2(hv, hv);
            }
        }
        if (s >= 1) {
#pragma unroll
            for (int r = 0; r < 2; r++) {
                int row = r0q + r;
                const float* gr = gbuf + row * GROW + GL2;
                float gi = gr[j2]       + gr[260 + j2] + gr[520 + j2] + gr[780 + j2];
                float gf = gr[64 + j2]  + gr[324 + j2] + gr[584 + j2] + gr[844 + j2];
                float gg = gr[128 + j2] + gr[388 + j2] + gr[648 + j2] + gr[908 + j2];
                float go = gr[192 + j2] + gr[452 + j2] + gr[712 + j2] + gr[972 + j2];
                float iv = sigm(gi);
                float fv = sigm(gf);
                float gv = tanh_(gg);
                float ov = sigm(go);
                c2s[r] = fv * c2s[r] + iv * gv;
                float hv = ov * tanh_(c2s[r]);
                *(float2*)&abuf[(256 + j2) * ST2 + 2 * row] = make_float2(hv, hv);
            }
        }
        if (s < T_LEN - 1) {
            *(float2*)&abuf[(xr_d0 + 0) * ST2 + 2 * xr_row] = make_float2(xreg.x, xreg.x);
            *(float2*)&abuf[(xr_d0 + 1) * ST2 + 2 * xr_row] = make_float2(xreg.y, xreg.y);
            *(float2*)&abuf[(xr_d0 + 2) * ST2 + 2 * xr_row] = make_float2(xreg.z, xreg.z);
            *(float2*)&abuf[(xr_d0 + 3) * ST2 + 2 * xr_row] = make_float2(xreg.w, xreg.w);
        }
        __syncthreads();   // abuf = [x(s+1), h1(s), h2(s-1)] ready
    }

    // ---- dense + relu on final h2 (abuf rows 256..319, dup'd) ----
    {
        int o  = t & 63;
        int r0 = (t >> 6) * 2;
        float bd = b_dense[o];
        float a0 = bd, a1 = bd;
        const float* wd = w_dense + o * 64;
#pragma unroll 8
        for (int k = 0; k < 64; k++) {
            float wv = wd[k];
            const float* h = &abuf[(256 + k) * ST2 + 2 * r0];
            a0 += wv * h[0];
            a1 += wv * h[2];
        }
        out[(b0 + r0 + 0) * OUTD + o] = fmaxf(a0, 0.0f);
        out[(b0 + r0 + 1) * OUTD + o] = fmaxf(a1, 0.0f);
    }
}

#define SMEM_BYTES ((AROWS * ST2 + 16 * GROW) * 4)

extern "C" void kernel_launch(void* const* d_in, const int* in_sizes, int n_in,
                              void* d_out, int out_size) {
    const float* x       = (const float*)d_in[0];
    const float* w_ih1   = (const float*)d_in[1];
    const float* w_hh1   = (const float*)d_in[2];
    const float* b_ih1   = (const float*)d_in[3];
    const float* b_hh1   = (const float*)d_in[4];
    const float* w_ih2   = (const float*)d_in[5];
    const float* w_hh2   = (const float*)d_in[6];
    const float* b_ih2   = (const float*)d_in[7];
    const float* b_hh2   = (const float*)d_in[8];
    const float* w_dense = (const float*)d_in[9];
    const float* b_dense = (const float*)d_in[10];
    float* out = (float*)d_out;

    static int attr_set = 0;
    if (!attr_set) {
        cudaFuncSetAttribute(lstm_main, cudaFuncAttributeMaxDynamicSharedMemorySize, SMEM_BYTES);
        attr_set = 1;
    }

    transpose_kernel<<<704, 256>>>(w_ih1, w_hh1, w_ih2, w_hh2);
    lstm_main<<<B_TOT / NB, NTH, SMEM_BYTES>>>(x, b_ih1, b_hh1, b_ih2, b_hh2,
                                               w_dense, b_dense, out);
}

// round 17
// speedup vs baseline: 1.7894x; 1.0049x over previous
#include <cuda_runtime.h>

// Fused 2-layer LSTM + dense. B=2048, T=128, D=H1=128, H2=64, OUT=64.
// grid=128 x 512 threads; one CTA per 16 batch rows.
// Layer 2 runs one timestep behind layer 1 (software pipeline): MM phase does
// gates1(s)+gates2(s-1) as one homogeneous block; E phase does both cell
// updates + stages x(s+1). 2 barriers/step.
// R15: L1-job weight stream uses a 3x4-row prefetch ring (12-row lead ~= L2
// latency) to kill the steady-state scoreboard stall on weight LDGs.

#define B_TOT 2048
#define T_LEN 128
#define D_IN  128
#define H1    128
#define H2    64
#define OUTD  64
#define NB    16
#define NTH   512
#define ST2   36     // dup'd activation row stride (floats): 32 data + 4 pad
#define AROWS 320    // abuf rows: x(128) + h1(128) + h2(64)
#define GROW  2080   // gbuf row stride: L1 2x520 + L2 4x260
#define GL2   1040   // L2 section base within a gbuf row

typedef unsigned long long ull;

// concatenated k-major weights: WCAT1[k][g] (256x512), WCAT2[k][g] (192x256)
__device__ float WCAT1[256 * 512];
__device__ float WCAT2[192 * 256];

__device__ __forceinline__ void fma2(ull &d, ull a, ull b) {
    asm("fma.rn.f32x2 %0, %1, %2, %0;" : "+l"(d) : "l"(a), "l"(b));
}
__device__ __forceinline__ ull pack2(float lo, float hi) {
    return (ull)__float_as_uint(lo) | ((ull)__float_as_uint(hi) << 32);
}
__device__ __forceinline__ float lo2(ull v) { return __uint_as_float((unsigned)v); }
__device__ __forceinline__ float hi2(ull v) { return __uint_as_float((unsigned)(v >> 32)); }

__device__ __forceinline__ float sigm(float v) {
    return __fdividef(1.0f, 1.0f + __expf(-v));
}
__device__ __forceinline__ float tanh_(float v) {
    return 2.0f * sigm(2.0f * v) - 1.0f;
}

// ---------------- weight transpose kernel ----------------
__global__ void transpose_kernel(const float* __restrict__ w_ih1,
                                 const float* __restrict__ w_hh1,
                                 const float* __restrict__ w_ih2,
                                 const float* __restrict__ w_hh2) {
    int idx = blockIdx.x * blockDim.x + threadIdx.x;
    if (idx < 65536) {                       // w_ih1 (512,128) -> WCAT1 rows 0-127
        int g = idx >> 7, k = idx & 127;
        WCAT1[k * 512 + g] = w_ih1[idx];
    } else if (idx < 131072) {               // w_hh1 (512,128) -> WCAT1 rows 128-255
        int i = idx - 65536; int g = i >> 7, k = i & 127;
        WCAT1[(128 + k) * 512 + g] = w_hh1[i];
    } else if (idx < 163840) {               // w_ih2 (256,128) -> WCAT2 rows 0-127
        int i = idx - 131072; int g = i >> 7, k = i & 127;
        WCAT2[k * 256 + g] = w_ih2[i];
    } else if (idx < 180224) {               // w_hh2 (256,64) -> WCAT2 rows 128-191
        int i = idx - 163840; int g = i >> 6, k = i & 63;
        WCAT2[(128 + k) * 256 + g] = w_hh2[i];
    }
}

// One k-row: 8 dup'd rows (4 broadcast LDS.128), 2 weight col-pairs. 16 FFMA2.
__device__ __forceinline__ void mmrow2(ull (&a0)[8], ull (&a1)[8],
                                       ulonglong2 w, const float* __restrict__ xr) {
    ulonglong2 a = *(const ulonglong2*)(xr + 0);
    ulonglong2 b = *(const ulonglong2*)(xr + 4);
    ulonglong2 c = *(const ulonglong2*)(xr + 8);
    ulonglong2 d = *(const ulonglong2*)(xr + 12);
    fma2(a0[0], a.x, w.x); fma2(a1[0], a.x, w.y);
    fma2(a0[1], a.y, w.x); fma2(a1[1], a.y, w.y);
    fma2(a0[2], b.x, w.x); fma2(a1[2], b.x, w.y);
    fma2(a0[3], b.y, w.x); fma2(a1[3], b.y, w.y);
    fma2(a0[4], c.x, w.x); fma2(a1[4], c.x, w.y);
    fma2(a0[5], c.y, w.x); fma2(a1[5], c.y, w.y);
    fma2(a0[6], d.x, w.x); fma2(a1[6], d.x, w.y);
    fma2(a0[7], d.y, w.x); fma2(a1[7], d.y, w.y);
}

// L1 job: K=128 k-rows with a 3-buffer x 4-row prefetch ring (12-row lead).
// Main loop guard-free to row 107; explicit 20-row epilogue. WSTR = u2/row.
template<int WSTR>
__device__ __forceinline__ void mmacc3_128(ull (&a0)[8], ull (&a1)[8],
                                           const ulonglong2* __restrict__ w,
                                           const float* __restrict__ xb) {
    ulonglong2 wb0[4], wb1[4], wb2[4];
#pragma unroll
    for (int u = 0; u < 4; u++) wb0[u] = w[u * WSTR];
#pragma unroll
    for (int u = 0; u < 4; u++) wb1[u] = w[(4 + u) * WSTR];
#pragma unroll
    for (int u = 0; u < 4; u++) wb2[u] = w[(8 + u) * WSTR];
#pragma unroll 1
    for (int kb = 0; kb <= 96; kb += 12) {   // 9 iters: consumes rows 0..107
#pragma unroll
        for (int u = 0; u < 4; u++) mmrow2(a0, a1, wb0[u], xb + (kb + u) * ST2);
#pragma unroll
        for (int u = 0; u < 4; u++) wb0[u] = w[(kb + 12 + u) * WSTR];
#pragma unroll
        for (int u = 0; u < 4; u++) mmrow2(a0, a1, wb1[u], xb + (kb + 4 + u) * ST2);
#pragma unroll
        for (int u = 0; u < 4; u++) wb1[u] = w[(kb + 16 + u) * WSTR];
#pragma unroll
        for (int u = 0; u < 4; u++) mmrow2(a0, a1, wb2[u], xb + (kb + 8 + u) * ST2);
#pragma unroll
        for (int u = 0; u < 4; u++) wb2[u] = w[(kb + 20 + u) * WSTR];
    }
    // epilogue: rows 108..127 (wb0=108-111, wb1=112-115, wb2=116-119 loaded)
#pragma unroll
    for (int u = 0; u < 4; u++) mmrow2(a0, a1, wb0[u], xb + (108 + u) * ST2);
#pragma unroll
    for (int u = 0; u < 4; u++) wb0[u] = w[(120 + u) * WSTR];
#pragma unroll
    for (int u = 0; u < 4; u++) mmrow2(a0, a1, wb1[u], xb + (112 + u) * ST2);
#pragma unroll
    for (int u = 0; u < 4; u++) wb1[u] = w[(124 + u) * WSTR];
#pragma unroll
    for (int u = 0; u < 4; u++) mmrow2(a0, a1, wb2[u], xb + (116 + u) * ST2);
#pragma unroll
    for (int u = 0; u < 4; u++) mmrow2(a0, a1, wb0[u], xb + (120 + u) * ST2);
#pragma unroll
    for (int u = 0; u < 4; u++) mmrow2(a0, a1, wb1[u], xb + (124 + u) * ST2);
}

// L2 job: K k-rows, classic 2-buffer prefetch (short job, keeps regs low).
template<int WSTR, int K>
__device__ __forceinline__ void mmacc(ull (&a0)[8], ull (&a1)[8],
                                      const ulonglong2* __restrict__ w,
                                      const float* __restrict__ xb) {
    ulonglong2 wb0[4], wb1[4];
#pragma unroll
    for (int u = 0; u < 4; u++) wb0[u] = w[u * WSTR];
#pragma unroll
    for (int u = 0; u < 4; u++) wb1[u] = w[(4 + u) * WSTR];
#pragma unroll 1
    for (int kb = 0; kb < K; kb += 8) {
#pragma unroll
        for (int u = 0; u < 4; u++) mmrow2(a0, a1, wb0[u], xb + (kb + u) * ST2);
        if (kb + 8 < K) {
#pragma unroll
            for (int u = 0; u < 4; u++) wb0[u] = w[(kb + 8 + u) * WSTR];
        }
#pragma unroll
        for (int u = 0; u < 4; u++) mmrow2(a0, a1, wb1[u], xb + (kb + 4 + u) * ST2);
        if (kb + 12 < K) {
#pragma unroll
            for (int u = 0; u < 4; u++) wb1[u] = w[(kb + 12 + u) * WSTR];
        }
    }
}

// stage 8 rows x 4 cols; lanes (consecutive q) give conflict-free STS.128.
__device__ __forceinline__ void stage8(float* gc, ull (&a0)[8], ull (&a1)[8]) {
#pragma unroll
    for (int r = 0; r < 8; r++)
        *(float4*)(gc + r * GROW) = make_float4(lo2(a0[r]), hi2(a0[r]),
                                                lo2(a1[r]), hi2(a1[r]));
}

// ---------------- main fused kernel ----------------
__global__ void __launch_bounds__(NTH, 1)
lstm_main(const float* __restrict__ x,
          const float* __restrict__ b_ih1, const float* __restrict__ b_hh1,
          const float* __restrict__ b_ih2, const float* __restrict__ b_hh2,
          const float* __restrict__ w_dense, const float* __restrict__ b_dense,
          float* __restrict__ out) {
    extern __shared__ float sm[];
    float* abuf = sm;                     // [320][ST2]: x | h1 | h2, dup'd
    float* gbuf = abuf + AROWS * ST2;     // [16][GROW] gate partial staging

    const int t  = threadIdx.x;
    const int b0 = blockIdx.x * NB;

    for (int i = t; i < AROWS * ST2 + 16 * GROW; i += NTH) sm[i] = 0.0f;

    // ---- MM-L1 role: t = kh1(1b) | rh1(1b) | q1(7b)
    const int q1  = t & 127;
    const int rh1 = (t >> 7) & 1;
    const int kh1 = (t >> 8) & 1;
    ull b1a = 0, b1b = 0;
    if (kh1 == 0) {
        b1a = pack2(b_ih1[4 * q1]     + b_hh1[4 * q1],
                    b_ih1[4 * q1 + 1] + b_hh1[4 * q1 + 1]);
        b1b = pack2(b_ih1[4 * q1 + 2] + b_hh1[4 * q1 + 2],
                    b_ih1[4 * q1 + 3] + b_hh1[4 * q1 + 3]);
    }

    // ---- MM-L2 role: t = kq2(2b) | rh2(1b) | q2(6b)
    const int q2  = t & 63;
    const int rh2 = (t >> 6) & 1;
    const int kq2 = t >> 7;               // 0..3
    ull b2a = 0, b2b = 0;
    if (kq2 == 0) {
        b2a = pack2(b_ih2[4 * q2]     + b_hh2[4 * q2],
                    b_ih2[4 * q2 + 1] + b_hh2[4 * q2 + 1]);
        b2b = pack2(b_ih2[4 * q2 + 2] + b_hh2[4 * q2 + 2],
                    b_ih2[4 * q2 + 3] + b_hh2[4 * q2 + 3]);
    }

    // ---- E roles
    const int j1  = t & 127;              // L1 unit, rows r0h..r0h+3
    const int r0h = (t >> 7) * 4;
    const int j2  = t & 63;               // L2 unit, rows r0q..r0q+1
    const int r0q = (t >> 6) * 2;

    float c1s[4], c2s[2];
#pragma unroll
    for (int i = 0; i < 4; i++) c1s[i] = 0.0f;
    c2s[0] = c2s[1] = 0.0f;

    // fully pre-offset matmul operands
    const ulonglong2* wL1 = (const ulonglong2*)WCAT1 + kh1 * 128 * 128 + q1;
    const float*      aL1 = abuf + (kh1 * 128) * ST2 + 16 * rh1;
    const ulonglong2* wL2 = (const ulonglong2*)WCAT2 + (kq2 * 48) * 64 + q2;
    const float*      aL2 = abuf + (128 + kq2 * 48) * ST2 + 16 * rh2;
    float* gL1 = gbuf + (rh1 * 8) * GROW + kh1 * 520 + 4 * q1;
    float* gL2 = gbuf + (rh2 * 8) * GROW + GL2 + kq2 * 260 + 4 * q2;

    // x staging role
    const int xr_row = t >> 5;            // 0..15
    const int xr_d0  = (t & 31) * 4;      // 0..124

    // prologue: stage x(0)
    {
        const float* xr = x + ((b0 + xr_row) * T_LEN + 0) * D_IN + xr_d0;
        float4 u = *(const float4*)xr;
        *(float2*)&abuf[(xr_d0 + 0) * ST2 + 2 * xr_row] = make_float2(u.x, u.x);
        *(float2*)&abuf[(xr_d0 + 1) * ST2 + 2 * xr_row] = make_float2(u.y, u.y);
        *(float2*)&abuf[(xr_d0 + 2) * ST2 + 2 * xr_row] = make_float2(u.z, u.z);
        *(float2*)&abuf[(xr_d0 + 3) * ST2 + 2 * xr_row] = make_float2(u.w, u.w);
    }
    __syncthreads();

#pragma unroll 1
    for (int s = 0; s <= T_LEN; ++s) {
        // prefetch x(s+1) into regs (consumed in E); hidden under MM
        float4 xreg;
        if (s < T_LEN - 1) {
            const float* xr = x + ((b0 + xr_row) * T_LEN + (s + 1)) * D_IN + xr_d0;
            xreg = *(const float4*)xr;
        }

        // ---- MM phase: gates1(s) and gates2(s-1) ----
        if (s < T_LEN) {
            ull a0[8], a1[8];
#pragma unroll
            for (int r = 0; r < 8; r++) { a0[r] = b1a; a1[r] = b1b; }
            mmacc3_128<128>(a0, a1, wL1, aL1);
            stage8(gL1, a0, a1);
        }
        if (s >= 1) {
            ull a0[8], a1[8];
#pragma unroll
            for (int r = 0; r < 8; r++) { a0[r] = b2a; a1[r] = b2b; }
            mmacc<64, 48>(a0, a1, wL2, aL2);
            stage8(gL2, a0, a1);
        }
        __syncthreads();   // gbuf complete; abuf reads done

        // ---- E phase: cell1(s), cell2(s-1), stage x(s+1) ----
        if (s < T_LEN) {
#pragma unroll
            for (int r = 0; r < 4; r++) {
                int row = r0h + r;
                const float* gr = gbuf + row * GROW;
                float gi = gr[j1]       + gr[520 + j1];
                float gf = gr[128 + j1] + gr[648 + j1];
                float gg = gr[256 + j1] + gr[776 + j1];
                float go = gr[384 + j1] + gr[904 + j1];
                float iv = sigm(gi);
                float fv = sigm(gf);
                float gv = tanh_(gg);
                float ov = sigm(go);
                c1s[r] = fv * c1s[r] + iv * gv;
                float hv = ov * tanh_(c1s[r]);
                *(float2*)&abuf[(128 + j1) * ST2 + 2 * row] = make_float2(hv, hv);
            }
        }
        if (s >= 1) {
#pragma unroll
            for (int r = 0; r < 2; r++) {
                int row = r0q + r;
                const float* gr = gbuf + row * GROW + GL2;
                float gi = gr[j2]       + gr[260 + j2] + gr[520 + j2] + gr[780 + j2];
                float gf = gr[64 + j2]  + gr[324 + j2] + gr[584 + j2] + gr[844 + j2];
                float gg = gr[128 + j2] + gr[388 + j2] + gr[648 + j2] + gr[908 + j2];
                float go = gr[192 + j2] + gr[452 + j2] + gr[712 + j2] + gr[972 + j2];
                float iv = sigm(gi);
                float fv = sigm(gf);
                float gv = tanh_(gg);
                float ov = sigm(go);
                c2s[r] = fv * c2s[r] + iv * gv;
                float hv = ov * tanh_(c2s[r]);
                *(float2*)&abuf[(256 + j2) * ST2 + 2 * row] = make_float2(hv, hv);
            }
        }
        if (s < T_LEN - 1) {
            *(float2*)&abuf[(xr_d0 + 0) * ST2 + 2 * xr_row] = make_float2(xreg.x, xreg.x);
            *(float2*)&abuf[(xr_d0 + 1) * ST2 + 2 * xr_row] = make_float2(xreg.y, xreg.y);
            *(float2*)&abuf[(xr_d0 + 2) * ST2 + 2 * xr_row] = make_float2(xreg.z, xreg.z);
            *(float2*)&abuf[(xr_d0 + 3) * ST2 + 2 * xr_row] = make_float2(xreg.w, xreg.w);
        }
        __syncthreads();   // abuf = [x(s+1), h1(s), h2(s-1)] ready
    }

    // ---- dense + relu on final h2 (abuf rows 256..319, dup'd) ----
    {
        int o  = t & 63;
        int r0 = (t >> 6) * 2;
        float bd = b_dense[o];
        float a0 = bd, a1 = bd;
        const float* wd = w_dense + o * 64;
#pragma unroll 8
        for (int k = 0; k < 64; k++) {
            float wv = wd[k];
            const float* h = &abuf[(256 + k) * ST2 + 2 * r0];
            a0 += wv * h[0];
            a1 += wv * h[2];
        }
        out[(b0 + r0 + 0) * OUTD + o] = fmaxf(a0, 0.0f);
        out[(b0 + r0 + 1) * OUTD + o] = fmaxf(a1, 0.0f);
    }
}

#define SMEM_BYTES ((AROWS * ST2 + 16 * GROW) * 4)

extern "C" void kernel_launch(void* const* d_in, const int* in_sizes, int n_in,
                              void* d_out, int out_size) {
    const float* x       = (const float*)d_in[0];
    const float* w_ih1   = (const float*)d_in[1];
    const float* w_hh1   = (const float*)d_in[2];
    const float* b_ih1   = (const float*)d_in[3];
    const float* b_hh1   = (const float*)d_in[4];
    const float* w_ih2   = (const float*)d_in[5];
    const float* w_hh2   = (const float*)d_in[6];
    const float* b_ih2   = (const float*)d_in[7];
    const float* b_hh2   = (const float*)d_in[8];
    const float* w_dense = (const float*)d_in[9];
    const float* b_dense = (const float*)d_in[10];
    float* out = (float*)d_out;

    static int attr_set = 0;
    if (!attr_set) {
        cudaFuncSetAttribute(lstm_main, cudaFuncAttributeMaxDynamicSharedMemorySize, SMEM_BYTES);
        attr_set = 1;
    }

    transpose_kernel<<<704, 256>>>(w_ih1, w_hh1, w_ih2, w_hh2);
    lstm_main<<<B_TOT / NB, NTH, SMEM_BYTES>>>(x, b_ih1, b_hh1, b_ih2, b_hh2,
                                               w_dense, b_dense, out);
}